// round 12
// baseline (speedup 1.0000x reference)
#include <cuda_runtime.h>
#include <math.h>
#include <cstdint>

// ---------------- problem constants ----------------
#define N_TOT   65536      // B*H*W
#define K_CB    512
#define C_DIM   64
#define B_DIM   64
#define HW      1024

#define TM      64         // rows per tile
#define THREADS 512
#define NTILES  1024
#define NCTAS   152        // GB300 SM count; persistent 1 CTA/SM
#define WROW    516        // wT row stride (floats): mult of 4 (16B rows), one-time 4-way STS

// output layout (floats), concatenation of the reference tuple
#define Q_OFF     0ULL
#define LOSS_OFF  4194304ULL
#define PERP_OFF  4194368ULL
#define ENC_OFF   4194369ULL
#define EIDX_OFF  37748801ULL
#define DIST_OFF  37814337ULL           // == 1 mod 4  ->  k == 3 mod 4 is 16B aligned
#define OUT_TOTAL 71368769

// smem layout (float indices)
// wT is SLOT-indexed: slot s holds code (s+3)&511  (cyclic shift by 3)
#define SM_WT    0                      // wT[64][516] = 33024 floats
#define SM_XR    33024                  // raw x tiles: 2 x 4096 floats (double buffer)
#define SM_WN    (SM_XR + 8192)         // wnorm_s[512] (slot-indexed), 16B aligned
#define SM_XN    (SM_WN + 512)          // xnorm[64]
#define SM_SIDX  (SM_XN + 64)           // int sidx[64]   (code)
#define SM_SSLOT (SM_SIDX + 64)         // int sslot[64]  (slot of code)
#define SM_CANB  (SM_SSLOT + 64)        // float candb[128]
#define SM_CANI  (SM_CANB + 128)        // int candi[128]
#define SM_RED   (SM_CANI + 128)        // float red[512]
#define SM_TOTF  (SM_RED + 512)
#define SMEM_BYTES (SM_TOTF * 4)        // ~171 KB -> 1 CTA/SM

__device__ float g_lpart[NTILES];
__device__ int   g_hist [K_CB];        // zero at load; last CTA re-zeroes each launch
__device__ int   g_done;               // arrival ticket; last CTA resets

typedef unsigned long long ull;

// ---------------- helpers ----------------
__device__ __forceinline__ ull pack2(float x) {
    ull r; asm("mov.b64 %0, {%1, %1};" : "=l"(r) : "f"(x)); return r;
}
__device__ __forceinline__ void fma2(ull &d, ull a, ull b) {
    asm("fma.rn.f32x2 %0, %1, %2, %3;" : "=l"(d) : "l"(a), "l"(b), "l"(d));
}
__device__ __forceinline__ void unpack2(ull v, float &lo, float &hi) {
    asm("mov.b64 {%0, %1}, %2;" : "=f"(lo), "=f"(hi) : "l"(v));
}
__device__ __forceinline__ uint32_t smem_u32(const void* p) {
    uint32_t a;
    asm("{ .reg .u64 t; cvta.to.shared.u64 t, %1; cvt.u32.u64 %0, t; }" : "=r"(a) : "l"(p));
    return a;
}
// lexicographic (d, idx): true if (d,i) < (D,I) -- preserves jnp.argmin tie-break
__device__ __forceinline__ int lexlt(float d, int i, float D, int I) {
    return (d < D) || (d == D && i < I);
}
#define CP_ASYNC16(sa, gp) asm volatile("cp.async.cg.shared.global [%0], [%1], 16;" :: "r"(sa), "l"(gp))
#define CP_COMMIT()        asm volatile("cp.async.commit_group;" ::: "memory")
#define CP_WAIT1()         asm volatile("cp.async.wait_group 1;" ::: "memory")
#define CP_WAIT0()         asm volatile("cp.async.wait_group 0;" ::: "memory")

// ---------------- single persistent kernel ----------------
extern "C" __global__ void __launch_bounds__(THREADS, 1)
vq_all(const float* __restrict__ inputs, const float* __restrict__ weight,
       float* __restrict__ out)
{
    extern __shared__ float smem[];
    float* wT    = smem + SM_WT;       // slot-indexed codebook transpose
    float* wnorm = smem + SM_WN;       // slot-indexed norms
    float* xnorm = smem + SM_XN;
    int*   sidx  = (int*)(smem + SM_SIDX);
    int*   sslot = (int*)(smem + SM_SSLOT);
    float* candb = smem + SM_CANB;
    int*   candi = (int*)(smem + SM_CANI);
    float* red   = smem + SM_RED;

    const uint32_t xr_sa = smem_u32(smem + SM_XR);
    const int tid  = threadIdx.x;
    const int warp = tid >> 5;
    const int lane = tid & 31;
    const int rowg = warp >> 1;            // rows rowg*8 .. +7
    const int kg   = warp & 1;             // slot half
    const int s0b  = kg * 256 + 4 * lane;  // slot groups s0b + 128*j, j=0,1 (4 slots each)
    const int cta  = blockIdx.x;

    // ---- prefetch first x tile (tile index = cta) into raw buffer 0 ----
    {
        const int t0 = cta;
        const float* src = inputs + (size_t)(t0 >> 4) * (C_DIM * HW) + (t0 & 15) * 64;
        for (int i = tid; i < 1024; i += THREADS) {
            int c = i >> 4, ro = (i & 15) * 4;
            CP_ASYNC16(xr_sa + (uint32_t)(c * 64 + ro) * 4, src + (size_t)c * HW + ro);
        }
        CP_COMMIT();
    }

    // ---- one-time: codebook -> slot-indexed transposed smem + wnorm ----
    for (int i = tid; i < K_CB * C_DIM; i += THREADS) {
        int s = i >> 6, c = i & 63;
        int k = (s + 3) & 511;             // slot -> code
        wT[c * WROW + s] = weight[k * C_DIM + c];
    }
    __syncthreads();
    {
        // wnorm_s[s] = sum_c wT[c][s]^2 (sequential fmaf: reference rounding per code)
        float s = 0.f;
        #pragma unroll
        for (int c = 0; c < C_DIM; c++) { float w = wT[c * WROW + tid]; s = fmaf(w, w, s); }
        wnorm[tid] = s;
    }

    // ---- persistent tile loop ----
    int buf = 0;
    for (int t = cta; t < NTILES; t += NCTAS) {
        // prefetch next tile into the other raw buffer (clamped -> redundant tile 0)
        {
            int tn = t + NCTAS; if (tn >= NTILES) tn = 0;
            const float* src = inputs + (size_t)(tn >> 4) * (C_DIM * HW) + (tn & 15) * 64;
            uint32_t dst = xr_sa + (uint32_t)((buf ^ 1) * 4096) * 4;
            for (int i = tid; i < 1024; i += THREADS) {
                int c = i >> 4, ro = (i & 15) * 4;
                CP_ASYNC16(dst + (uint32_t)(c * 64 + ro) * 4, src + (size_t)c * HW + ro);
            }
            CP_COMMIT();
        }
        CP_WAIT1();            // oldest group (current buffer) complete
        __syncthreads();

        const float* xrb = smem + SM_XR + buf * 4096;   // raw xs[c][r]

        // xnorm for this tile (sequential fmaf rounding)
        if (tid < TM) {
            float s = 0.f;
            #pragma unroll
            for (int c = 0; c < C_DIM; c++) { float x = xrb[c * 64 + tid]; s = fmaf(x, x, s); }
            xnorm[tid] = s;
        }
        __syncthreads();

        // ---- mainloop: 8 rows x 8 slots per thread; B via 2x LDS.128 ----
        ull acc[8][4];
        #pragma unroll
        for (int r = 0; r < 8; r++)
            #pragma unroll
            for (int j = 0; j < 4; j++) acc[r][j] = 0ULL;

        const float* arow = xrb + rowg * 8;
        const float* bcol = wT + s0b;

        #pragma unroll 4
        for (int c = 0; c < C_DIM; c++) {
            const float4 a0 = *(const float4*)(arow + c * 64);
            const float4 a1 = *(const float4*)(arow + c * 64 + 4);
            ull aa[8];
            aa[0] = pack2(a0.x); aa[1] = pack2(a0.y); aa[2] = pack2(a0.z); aa[3] = pack2(a0.w);
            aa[4] = pack2(a1.x); aa[5] = pack2(a1.y); aa[6] = pack2(a1.z); aa[7] = pack2(a1.w);
            const float* bp = bcol + c * WROW;
            ulonglong2 v0 = *(const ulonglong2*)(bp);          // slots s0b..s0b+3
            ulonglong2 v1 = *(const ulonglong2*)(bp + 128);    // slots s0b+128..+131
            ull bb[4] = { v0.x, v0.y, v1.x, v1.y };
            #pragma unroll
            for (int r = 0; r < 8; r++)
                #pragma unroll
                for (int j = 0; j < 4; j++) fma2(acc[r][j], aa[r], bb[j]);
        }

        const int n0   = t * TM;
        const int bimg = t >> 4;
        const int p0   = (t & 15) * 64;

        // ---- epilogue: distances (reference rounding), lex argmin, aligned stores ----
        const float INF = __int_as_float(0x7f800000);
        #pragma unroll
        for (int r = 0; r < 8; r++) {
            const int row = rowg * 8 + r;
            const int n   = n0 + row;
            const float xn = xnorm[row];

            float best = INF; int bidx = 0x7fffffff;
            float* dptr = out + DIST_OFF + (size_t)n * K_CB;
            #pragma unroll
            for (int j = 0; j < 2; j++) {
                const int s0 = s0b + 128 * j;
                const float4 wn = *(const float4*)(wnorm + s0);   // LDS.128, aligned
                float z0, z1, z2, z3;
                unpack2(acc[r][2 * j],     z0, z1);
                unpack2(acc[r][2 * j + 1], z2, z3);
                float d0 = (xn + wn.x) - 2.0f * z0;
                float d1 = (xn + wn.y) - 2.0f * z1;
                float d2 = (xn + wn.z) - 2.0f * z2;
                float d3 = (xn + wn.w) - 2.0f * z3;
                const int kc = s0 + 3;                  // first code of group
                const int k0 = kc & 511, k1 = (kc + 1) & 511;
                const int k2 = (kc + 2) & 511, k3 = (kc + 3) & 511;
                if (lexlt(d0, k0, best, bidx)) { best = d0; bidx = k0; }
                if (lexlt(d1, k1, best, bidx)) { best = d1; bidx = k1; }
                if (lexlt(d2, k2, best, bidx)) { best = d2; bidx = k2; }
                if (lexlt(d3, k3, best, bidx)) { best = d3; bidx = k3; }
                if (s0 != 508) {
                    __stcs((float4*)(dptr + kc), make_float4(d0, d1, d2, d3));  // 16B aligned
                } else {                                   // wrap group: codes 511,0,1,2
                    __stcs(dptr + 511, d0);
                    __stcs(dptr + 0,   d1);
                    __stcs(dptr + 1,   d2);
                    __stcs(dptr + 2,   d3);
                }
            }
            #pragma unroll
            for (int off = 16; off > 0; off >>= 1) {
                float ob = __shfl_xor_sync(0xffffffffu, best, off);
                int   oi = __shfl_xor_sync(0xffffffffu, bidx, off);
                if (lexlt(ob, oi, best, bidx)) { best = ob; bidx = oi; }
            }
            if (lane == 0) { candb[row * 2 + kg] = best; candi[row * 2 + kg] = bidx; }
        }
        __syncthreads();

        // combine slot-half candidates (index ranges overlap across halves -> lex)
        if (tid < TM) {
            float b0 = candb[tid * 2], b1 = candb[tid * 2 + 1];
            int   i0 = candi[tid * 2], i1 = candi[tid * 2 + 1];
            int bi; float bd;
            if (lexlt(b1, i1, b0, i0)) { bd = b1; bi = i1; } else { bd = b0; bi = i0; }
            (void)bd;
            sidx[tid]  = bi;
            sslot[tid] = (bi + 509) & 511;            // code -> slot
            out[EIDX_OFF + (size_t)(n0 + tid)] = (float)bi;
            atomicAdd(&g_hist[bi], 1);                // int atomics: order-independent
        }
        __syncthreads();

        // encodings one-hot rows: vectorized interior (k=3..506 in float4) + 4 scalars
        {
            float* ebase = out + ENC_OFF + (size_t)n0 * K_CB;
            #pragma unroll
            for (int rr = 0; rr < 4; rr++) {
                const int row = warp * 4 + rr;
                const int sv  = sidx[row];
                float* rbase = ebase + (size_t)row * K_CB;
                #pragma unroll
                for (int m = lane; m < 127; m += 32) {
                    const int k = 3 + 4 * m;
                    float4 v;
                    v.x = (sv == k)     ? 1.0f : 0.0f;
                    v.y = (sv == k + 1) ? 1.0f : 0.0f;
                    v.z = (sv == k + 2) ? 1.0f : 0.0f;
                    v.w = (sv == k + 3) ? 1.0f : 0.0f;
                    __stcs((float4*)(rbase + k), v);   // 16B aligned (ENC_OFF odd + 3)
                }
                if (lane < 3)       rbase[lane] = (sv == lane) ? 1.0f : 0.0f;
                else if (lane == 3) rbase[511]  = (sv == 511)  ? 1.0f : 0.0f;
            }
        }

        // q_out (straight-through: x + (q - x)), float4 stores + fused loss partial
        float* qbase = out + (size_t)bimg * (C_DIM * HW) + p0;
        float s = 0.f;
        #pragma unroll
        for (int i = tid; i < 1024; i += THREADS) {
            const int c = i >> 4, p4 = (i & 15) * 4;
            float4 x4 = *(const float4*)(xrb + c * 64 + p4);
            const float* wrow = wT + c * WROW;
            float4 o;
            float d0 = wrow[sslot[p4]]     - x4.x;     // slot-indexed gathers
            float d1 = wrow[sslot[p4 + 1]] - x4.y;
            float d2 = wrow[sslot[p4 + 2]] - x4.z;
            float d3 = wrow[sslot[p4 + 3]] - x4.w;
            o.x = x4.x + d0; o.y = x4.y + d1; o.z = x4.z + d2; o.w = x4.w + d3;
            __stcs((float4*)(qbase + (size_t)c * HW + p4), o);
            s = fmaf(d0, d0, s); s = fmaf(d1, d1, s);
            s = fmaf(d2, d2, s); s = fmaf(d3, d3, s);
        }
        // loss partial: warp shuffle tree + 16-way combine (deterministic fixed order)
        #pragma unroll
        for (int off = 16; off > 0; off >>= 1) s += __shfl_xor_sync(0xffffffffu, s, off);
        if (lane == 0) red[warp] = s;
        __syncthreads();
        if (warp == 0) {
            float v = (lane < 16) ? red[lane] : 0.f;
            #pragma unroll
            for (int off = 8; off > 0; off >>= 1) v += __shfl_xor_sync(0xffffffffu, v, off);
            if (lane == 0) g_lpart[t] = v;
        }
        __syncthreads();         // protects smem reuse + buffer recycling next iter

        buf ^= 1;
    }
    CP_WAIT0();                  // drain any abandoned prefetch

    // ---- fused finish: last CTA computes loss + perplexity ----
    __shared__ int s_last;
    if (tid == 0) {
        __threadfence();
        int tk = atomicAdd(&g_done, 1);
        s_last = (tk == NCTAS - 1);
    }
    __syncthreads();
    if (s_last) {
        if (tid == 0) g_done = 0;                 // reset for graph replay
        if (tid < B_DIM) {
            float s = 0.f;
            #pragma unroll
            for (int j = 0; j < 16; j++) s += g_lpart[tid * 16 + j];   // fixed order
            out[LOSS_OFF + tid] = 1.25f * (s * (1.0f / 65536.0f));
        }
        int h = g_hist[tid];
        g_hist[tid] = 0;                          // restore zero invariant
        float p = (float)h * (1.0f / 65536.0f);
        red[tid] = -p * logf(p + 1e-10f);
        __syncthreads();
        #pragma unroll
        for (int off = 256; off > 0; off >>= 1) {
            if (tid < off) red[tid] += red[tid + off];
            __syncthreads();
        }
        if (tid == 0) out[PERP_OFF] = expf(red[0]);
    }
}

// ---------------- launch ----------------
extern "C" void kernel_launch(void* const* d_in, const int* in_sizes, int n_in,
                              void* d_out, int out_size)
{
    const float* inputs = (const float*)d_in[0];
    const float* weight = (const float*)d_in[1];
    float* out = (float*)d_out;

    if (out_size != OUT_TOTAL) return;

    cudaFuncSetAttribute(vq_all, cudaFuncAttributeMaxDynamicSharedMemorySize, SMEM_BYTES);

    vq_all<<<NCTAS, THREADS, SMEM_BYTES>>>(inputs, weight, out);
}

// round 13
// speedup vs baseline: 1.1519x; 1.1519x over previous
#include <cuda_runtime.h>
#include <math.h>
#include <cstdint>

// ---------------- problem constants ----------------
#define N_TOT   65536      // B*H*W
#define K_CB    512
#define C_DIM   64
#define B_DIM   64
#define HW      1024

#define TM      64         // rows per tile (16 warps x 4 rows)
#define THREADS 512
#define NTILES  1024
#define NCTAS   152        // persistent, 1 CTA/SM
#define WROW    514        // wT row stride (floats)

// output layout (floats), concatenation of the reference tuple
#define Q_OFF     0ULL
#define LOSS_OFF  4194304ULL
#define PERP_OFF  4194368ULL
#define ENC_OFF   4194369ULL
#define EIDX_OFF  37748801ULL
#define DIST_OFF  37814337ULL
#define OUT_TOTAL 71368769

// smem layout (float indices)
#define SM_WT   0                      // wT[64][514] = 32896 floats
#define SM_XW   32896                  // per-warp x slices: 16 warps x 2 bufs x 256 = 8192
#define SM_WN   (SM_XW + 8192)         // wnorm[512]
#define SM_RED  (SM_WN + 512)          // float red[512] (finish only)
#define SM_TOTF (SM_RED + 512)
#define SMEM_BYTES (SM_TOTF * 4)       // ~168 KB -> 1 CTA/SM

__device__ float g_lp[NTILES * 16];    // per (tile, warp) loss partial
__device__ int   g_hist[K_CB];         // zero at load; last CTA re-zeroes each launch
__device__ int   g_done;               // arrival ticket; last CTA resets

typedef unsigned long long ull;

// ---------------- helpers ----------------
__device__ __forceinline__ ull pack2(float x) {
    ull r; asm("mov.b64 %0, {%1, %1};" : "=l"(r) : "f"(x)); return r;
}
__device__ __forceinline__ void fma2(ull &d, ull a, ull b) {
    asm("fma.rn.f32x2 %0, %1, %2, %3;" : "=l"(d) : "l"(a), "l"(b), "l"(d));
}
__device__ __forceinline__ void unpack2(ull v, float &lo, float &hi) {
    asm("mov.b64 {%0, %1}, %2;" : "=f"(lo), "=f"(hi) : "l"(v));
}
__device__ __forceinline__ uint32_t smem_u32(const void* p) {
    uint32_t a;
    asm("{ .reg .u64 t; cvta.to.shared.u64 t, %1; cvt.u32.u64 %0, t; }" : "=r"(a) : "l"(p));
    return a;
}
#define CP_ASYNC16(sa, gp) asm volatile("cp.async.cg.shared.global [%0], [%1], 16;" :: "r"(sa), "l"(gp))
#define CP_COMMIT()        asm volatile("cp.async.commit_group;" ::: "memory")
#define CP_WAIT1()         asm volatile("cp.async.wait_group 1;" ::: "memory")
#define CP_WAIT0()         asm volatile("cp.async.wait_group 0;" ::: "memory")

// ---------------- single persistent kernel, free-running warps ----------------
extern "C" __global__ void __launch_bounds__(THREADS, 1)
vq_all(const float* __restrict__ inputs, const float* __restrict__ weight,
       float* __restrict__ out)
{
    extern __shared__ float smem[];
    float* wT    = smem + SM_WT;       // wT[c][k]
    float* wnorm = smem + SM_WN;
    float* red   = smem + SM_RED;

    const int tid  = threadIdx.x;
    const int warp = tid >> 5;         // warp owns rows 4*warp .. 4*warp+3 of every tile
    const int lane = tid & 31;
    const int cta  = blockIdx.x;

    float* xw_base = smem + SM_XW + warp * 512;         // 2 slices x 256 floats
    const uint32_t xw_sa = smem_u32(xw_base);

    // per-thread cp.async channels: this thread copies c = lane and c = lane+32
    const int c0 = lane, c1 = lane + 32;

    // ---- prefetch first tile's slice into buf 0 ----
    {
        const int t0 = cta;
        const float* src = inputs + (size_t)(t0 >> 4) * (C_DIM * HW)
                         + (t0 & 15) * 64 + 4 * warp;
        CP_ASYNC16(xw_sa + (uint32_t)(c0 * 4) * 4, src + (size_t)c0 * HW);
        CP_ASYNC16(xw_sa + (uint32_t)(c1 * 4) * 4, src + (size_t)c1 * HW);
        CP_COMMIT();
    }

    // ---- one-time: weight transpose + wnorm (the only CTA barriers) ----
    for (int i = tid; i < K_CB * C_DIM; i += THREADS) {
        int k = i >> 6, c = i & 63;
        wT[c * WROW + k] = weight[i];
    }
    __syncthreads();
    {
        float s = 0.f;
        #pragma unroll
        for (int c = 0; c < C_DIM; c++) { float w = wT[c * WROW + tid]; s = fmaf(w, w, s); }
        wnorm[tid] = s;
    }
    __syncthreads();

    // ---- per-warp persistent tile loop (no CTA barriers inside) ----
    int buf = 0;
    for (int t = cta; t < NTILES; t += NCTAS) {
        // prefetch next tile's slice into the other buffer
        {
            int tn = t + NCTAS; if (tn >= NTILES) tn = 0;
            const float* src = inputs + (size_t)(tn >> 4) * (C_DIM * HW)
                             + (tn & 15) * 64 + 4 * warp;
            uint32_t dst = xw_sa + (uint32_t)((buf ^ 1) * 256) * 4;
            CP_ASYNC16(dst + (uint32_t)(c0 * 4) * 4, src + (size_t)c0 * HW);
            CP_ASYNC16(dst + (uint32_t)(c1 * 4) * 4, src + (size_t)c1 * HW);
            CP_COMMIT();
        }
        CP_WAIT1();                    // this thread's copies for current buffer done
        __syncwarp();                  // all lanes' copies visible warp-wide

        const float* slice = xw_base + buf * 256;   // [c][4] floats

        // xnorm for own rows: lane r (<4) computes row r (sequential fmaf rounding)
        float xn_own = 0.f;
        if (lane < 4) {
            #pragma unroll
            for (int c = 0; c < C_DIM; c++) {
                float x = slice[c * 4 + lane];
                xn_own = fmaf(x, x, xn_own);
            }
        }

        // ---- mainloop: 4 rows x 16 codes per lane; codes k = 2*lane + 64*j ----
        ull acc[4][8];
        #pragma unroll
        for (int r = 0; r < 4; r++)
            #pragma unroll
            for (int j = 0; j < 8; j++) acc[r][j] = 0ULL;

        const ull* bbase = (const ull*)(wT + 2 * lane);

        #pragma unroll 4
        for (int c = 0; c < C_DIM; c++) {
            const float4 av = *(const float4*)(slice + c * 4);   // broadcast
            ull a0 = pack2(av.x), a1 = pack2(av.y), a2 = pack2(av.z), a3 = pack2(av.w);
            const ull* bp = bbase + (size_t)c * (WROW / 2);
            ull bb[8];
            #pragma unroll
            for (int j = 0; j < 8; j++) bb[j] = bp[32 * j];      // conflict-free LDS.64
            #pragma unroll
            for (int j = 0; j < 8; j++) {
                fma2(acc[0][j], a0, bb[j]);
                fma2(acc[1][j], a1, bb[j]);
                fma2(acc[2][j], a2, bb[j]);
                fma2(acc[3][j], a3, bb[j]);
            }
        }

        const int n0   = t * TM + 4 * warp;       // first row owned by this warp
        const int bimg = t >> 4;
        const int p0   = (t & 15) * 64 + 4 * warp;

        // ---- epilogue: distances (reference rounding) + full-K warp argmin ----
        const float INF = __int_as_float(0x7f800000);
        int   bi_r[4];
        #pragma unroll
        for (int r = 0; r < 4; r++) {
            const int n = n0 + r;
            const float xn = __shfl_sync(0xffffffffu, xn_own, r);

            float best = INF; int bidx = 0;
            float* dptr = out + DIST_OFF + (size_t)n * K_CB;
            #pragma unroll
            for (int j = 0; j < 8; j++) {
                float zlo, zhi; unpack2(acc[r][j], zlo, zhi);
                const int k0 = 2 * lane + 64 * j;
                const float2 wn2 = *(const float2*)(wnorm + k0);  // LDS.64 aligned
                float dlo = (xn + wn2.x) - 2.0f * zlo;
                float dhi = (xn + wn2.y) - 2.0f * zhi;
                __stcs(dptr + k0,     dlo);                       // coalesced pairs
                __stcs(dptr + k0 + 1, dhi);
                if (dlo < best) { best = dlo; bidx = k0; }        // ascending k, strict '<'
                if (dhi < best) { best = dhi; bidx = k0 + 1; }    // -> lowest index on ties
            }
            #pragma unroll
            for (int off = 16; off > 0; off >>= 1) {
                float ob = __shfl_xor_sync(0xffffffffu, best, off);
                int   oi = __shfl_xor_sync(0xffffffffu, bidx, off);
                if (ob < best || (ob == best && oi < bidx)) { best = ob; bidx = oi; }
            }
            bi_r[r] = bidx;                                      // all lanes agree
            if (lane == 0) {
                out[EIDX_OFF + (size_t)n] = (float)bidx;
                atomicAdd(&g_hist[bidx], 1);                     // order-independent
            }
        }

        // ---- encodings one-hot for own 4 rows: float4 interior + 4 scalars ----
        {
            float* ebase = out + ENC_OFF + (size_t)n0 * K_CB;
            #pragma unroll
            for (int r = 0; r < 4; r++) {
                const int sv = bi_r[r];
                float* rbase = ebase + (size_t)r * K_CB;
                #pragma unroll
                for (int m = lane; m < 127; m += 32) {
                    const int k = 3 + 4 * m;
                    float4 v;
                    v.x = (sv == k)     ? 1.0f : 0.0f;
                    v.y = (sv == k + 1) ? 1.0f : 0.0f;
                    v.z = (sv == k + 2) ? 1.0f : 0.0f;
                    v.w = (sv == k + 3) ? 1.0f : 0.0f;
                    __stcs((float4*)(rbase + k), v);   // 16B aligned (ENC_OFF odd + 3)
                }
                if (lane < 3)       rbase[lane] = (sv == lane) ? 1.0f : 0.0f;
                else if (lane == 3) rbase[511]  = (sv == 511)  ? 1.0f : 0.0f;
            }
        }

        // ---- q_out for own rows (x + (q - x)) + loss partial; 2 c per lane ----
        float s = 0.f;
        float* qbase = out + (size_t)bimg * (C_DIM * HW) + p0;
        #pragma unroll
        for (int cc = 0; cc < 2; cc++) {
            const int c = cc ? c1 : c0;
            float4 x4 = *(const float4*)(slice + c * 4);
            const float* wrow = wT + c * WROW;
            float d0 = wrow[bi_r[0]] - x4.x;
            float d1 = wrow[bi_r[1]] - x4.y;
            float d2 = wrow[bi_r[2]] - x4.z;
            float d3 = wrow[bi_r[3]] - x4.w;
            float4 o;
            o.x = x4.x + d0; o.y = x4.y + d1; o.z = x4.z + d2; o.w = x4.w + d3;
            __stcs((float4*)(qbase + (size_t)c * HW), o);        // 16B aligned
            s = fmaf(d0, d0, s); s = fmaf(d1, d1, s);
            s = fmaf(d2, d2, s); s = fmaf(d3, d3, s);
        }
        #pragma unroll
        for (int off = 16; off > 0; off >>= 1) s += __shfl_xor_sync(0xffffffffu, s, off);
        if (lane == 0) g_lp[t * 16 + warp] = s;

        __syncwarp();                  // slice reads done before next-iter prefetch reuse
        buf ^= 1;
    }
    CP_WAIT0();                        // drain dangling prefetch

    // ---- fused finish: last CTA computes loss + perplexity ----
    __syncthreads();
    __shared__ int s_last;
    if (tid == 0) {
        __threadfence();
        s_last = (atomicAdd(&g_done, 1) == NCTAS - 1);
    }
    __syncthreads();
    if (s_last) {
        if (tid == 0) g_done = 0;                 // reset for graph replay
        if (tid < B_DIM) {
            float s = 0.f;
            #pragma unroll
            for (int j = 0; j < 16; j++)          // tiles of batch, fixed order
                #pragma unroll
                for (int w = 0; w < 16; w++)      // warp partials, fixed order
                    s += g_lp[(tid * 16 + j) * 16 + w];
            out[LOSS_OFF + tid] = 1.25f * (s * (1.0f / 65536.0f));
        }
        int h = g_hist[tid];
        g_hist[tid] = 0;                          // restore zero invariant
        float p = (float)h * (1.0f / 65536.0f);
        red[tid] = -p * logf(p + 1e-10f);
        __syncthreads();
        #pragma unroll
        for (int off = 256; off > 0; off >>= 1) {
            if (tid < off) red[tid] += red[tid + off];
            __syncthreads();
        }
        if (tid == 0) out[PERP_OFF] = expf(red[0]);
    }
}

// ---------------- launch ----------------
extern "C" void kernel_launch(void* const* d_in, const int* in_sizes, int n_in,
                              void* d_out, int out_size)
{
    const float* inputs = (const float*)d_in[0];
    const float* weight = (const float*)d_in[1];
    float* out = (float*)d_out;

    if (out_size != OUT_TOTAL) return;

    cudaFuncSetAttribute(vq_all, cudaFuncAttributeMaxDynamicSharedMemorySize, SMEM_BYTES);

    vq_all<<<NCTAS, THREADS, SMEM_BYTES>>>(inputs, weight, out);
}